// round 1
// baseline (speedup 1.0000x reference)
#include <cuda_runtime.h>
#include <math.h>

// Problem constants
#define Bc     16
#define L1c    512
#define L2c    512
#define Dc     512
#define Hc     8
#define INNERc 1024
#define HDc    128
#define DCc    640   // D + HD

// ---------------- scratch (static device globals; no allocation) -------------
__device__ float g_T  [(size_t)Bc*Hc*L1c*Dc];     // P @ W_aff[h]       (B,H,L1,D)
__device__ float g_aff[(size_t)Bc*Hc*L1c*L2c];    // tanh(T @ S^T)*mask (B,H,L1,L2)
__device__ float g_PP [(size_t)Bc*L1c*INNERc];    // P @ W_p            (B,L1,INNER)
__device__ float g_PS [(size_t)Bc*L2c*INNERc];    // S @ W_s            (B,L2,INNER)
__device__ float g_wp [(size_t)Bc*Hc*L2c*HDc];    // relu(aff^T @ pp)   (B,H,L2,HD)
__device__ float g_ws [(size_t)Bc*Hc*L1c*HDc];    // relu(aff  @ ps)    (B,H,L1,HD)
__device__ float g_poolp[(size_t)Bc*L2c*HDc];     // max_h wp
__device__ float g_pools[(size_t)Bc*L1c*HDc];     // max_h ws
__device__ float g_catp[(size_t)Bc*L1c*DCc];      // [P, pool_s]
__device__ float g_cats[(size_t)Bc*L2c*DCc];      // [S, pool_p]

// ---------------- tiled fp32 SGEMM core --------------------------------------
// 128x128 block tile, BK=16, 256 threads, 8x8 per-thread microtile.
// TRA: A stored [K,M] (TN case, direct As load).  !TRA: A stored [M,K].
// TRB: B stored [N,K] (NT case).                  !TRB: B stored [K,N].
constexpr int BM = 128, BN = 128, BK = 16;

template<bool TRA, bool TRB>
__device__ __forceinline__ void sgemm_block(
    const float* __restrict__ A, const float* __restrict__ Bp,
    int K, int lda, int ldb, float (&acc)[8][8])
{
    __shared__ float As[BK][BM + 4];
    __shared__ float Bs[BK][BN + 4];

    const int tid  = threadIdx.x;
    const int row0 = blockIdx.y * BM;
    const int col0 = blockIdx.x * BN;
    const int ty8  = (tid >> 4) << 3;
    const int tx8  = (tid & 15) << 3;

    #pragma unroll
    for (int i = 0; i < 8; i++)
        #pragma unroll
        for (int j = 0; j < 8; j++) acc[i][j] = 0.f;

    for (int k0 = 0; k0 < K; k0 += BK) {
        // ---- load A tile -> As[k][m] ----
        #pragma unroll
        for (int r = 0; r < 2; r++) {
            int lid = tid + r * 256;
            if (!TRA) {
                int m  = lid >> 2;            // 0..127
                int kq = (lid & 3) << 2;      // 0,4,8,12
                float4 v = *(const float4*)(A + (size_t)(row0 + m) * lda + (k0 + kq));
                As[kq + 0][m] = v.x; As[kq + 1][m] = v.y;
                As[kq + 2][m] = v.z; As[kq + 3][m] = v.w;
            } else {
                int kk = lid >> 5;            // 0..15
                int m  = (lid & 31) << 2;     // 0..124
                float4 v = *(const float4*)(A + (size_t)(k0 + kk) * lda + (row0 + m));
                *(float4*)&As[kk][m] = v;
            }
        }
        // ---- load B tile -> Bs[k][n] ----
        #pragma unroll
        for (int r = 0; r < 2; r++) {
            int lid = tid + r * 256;
            if (TRB) {
                int n  = lid >> 2;
                int kq = (lid & 3) << 2;
                float4 v = *(const float4*)(Bp + (size_t)(col0 + n) * ldb + (k0 + kq));
                Bs[kq + 0][n] = v.x; Bs[kq + 1][n] = v.y;
                Bs[kq + 2][n] = v.z; Bs[kq + 3][n] = v.w;
            } else {
                int kk = lid >> 5;
                int n  = (lid & 31) << 2;
                float4 v = *(const float4*)(Bp + (size_t)(k0 + kk) * ldb + (col0 + n));
                *(float4*)&Bs[kk][n] = v;
            }
        }
        __syncthreads();

        #pragma unroll
        for (int k = 0; k < BK; k++) {
            float a[8], bb[8];
            *(float4*)&a[0]  = *(const float4*)&As[k][ty8];
            *(float4*)&a[4]  = *(const float4*)&As[k][ty8 + 4];
            *(float4*)&bb[0] = *(const float4*)&Bs[k][tx8];
            *(float4*)&bb[4] = *(const float4*)&Bs[k][tx8 + 4];
            #pragma unroll
            for (int i = 0; i < 8; i++)
                #pragma unroll
                for (int j = 0; j < 8; j++)
                    acc[i][j] = fmaf(a[i], bb[j], acc[i][j]);
        }
        __syncthreads();
    }
}

__device__ __forceinline__ void store_tile(float* C, int ldc, const float (&acc)[8][8]) {
    int row0 = blockIdx.y * BM + ((threadIdx.x >> 4) << 3);
    int col0 = blockIdx.x * BN + ((threadIdx.x & 15) << 3);
    #pragma unroll
    for (int i = 0; i < 8; i++) {
        *(float4*)(C + (size_t)(row0 + i) * ldc + col0)     = make_float4(acc[i][0], acc[i][1], acc[i][2], acc[i][3]);
        *(float4*)(C + (size_t)(row0 + i) * ldc + col0 + 4) = make_float4(acc[i][4], acc[i][5], acc[i][6], acc[i][7]);
    }
}

__device__ __forceinline__ void store_tile_relu(float* C, int ldc, const float (&acc)[8][8]) {
    int row0 = blockIdx.y * BM + ((threadIdx.x >> 4) << 3);
    int col0 = blockIdx.x * BN + ((threadIdx.x & 15) << 3);
    #pragma unroll
    for (int i = 0; i < 8; i++) {
        float v[8];
        #pragma unroll
        for (int j = 0; j < 8; j++) v[j] = fmaxf(acc[i][j], 0.f);
        *(float4*)(C + (size_t)(row0 + i) * ldc + col0)     = make_float4(v[0], v[1], v[2], v[3]);
        *(float4*)(C + (size_t)(row0 + i) * ldc + col0 + 4) = make_float4(v[4], v[5], v[6], v[7]);
    }
}

// ---------------- stage kernels ----------------------------------------------

// 1) T[b,h] = P[b] @ W_aff[h]     grid(4,4,128)
__global__ __launch_bounds__(256) void k_pw(const float* __restrict__ P,
                                            const float* __restrict__ Waff) {
    int bh = blockIdx.z;
    float acc[8][8];
    sgemm_block<false, false>(P + (size_t)(bh >> 3) * L1c * Dc,
                              Waff + (size_t)(bh & 7) * Dc * Dc,
                              Dc, Dc, Dc, acc);
    store_tile(g_T + (size_t)bh * L1c * Dc, Dc, acc);
}

// 2) aff[b,h] = tanh(T[b,h] @ S[b]^T) * mask     grid(4,4,128)
__global__ __launch_bounds__(256) void k_aff(const float* __restrict__ S,
                                             const float* __restrict__ pm,
                                             const float* __restrict__ sm) {
    int bh = blockIdx.z, b = bh >> 3;
    float acc[8][8];
    sgemm_block<false, true>(g_T + (size_t)bh * L1c * Dc,
                             S + (size_t)b * L2c * Dc,
                             Dc, Dc, Dc, acc);
    int row0 = blockIdx.y * BM + ((threadIdx.x >> 4) << 3);
    int col0 = blockIdx.x * BN + ((threadIdx.x & 15) << 3);
    float* C = g_aff + (size_t)bh * L1c * L2c;
    float smv[8];
    #pragma unroll
    for (int j = 0; j < 8; j++) smv[j] = sm[b * L2c + col0 + j];
    #pragma unroll
    for (int i = 0; i < 8; i++) {
        float pmv = pm[b * L1c + row0 + i];
        float v[8];
        #pragma unroll
        for (int j = 0; j < 8; j++) v[j] = tanhf(acc[i][j]) * pmv * smv[j];
        *(float4*)(C + (size_t)(row0 + i) * L2c + col0)     = make_float4(v[0], v[1], v[2], v[3]);
        *(float4*)(C + (size_t)(row0 + i) * L2c + col0 + 4) = make_float4(v[4], v[5], v[6], v[7]);
    }
}

// 3) projections: PP = P @ W_p, PS = S @ W_s     grid(8,4,16)
__global__ __launch_bounds__(256) void k_projP(const float* __restrict__ X,
                                               const float* __restrict__ W) {
    int b = blockIdx.z;
    float acc[8][8];
    sgemm_block<false, false>(X + (size_t)b * L1c * Dc, W, Dc, Dc, INNERc, acc);
    store_tile(g_PP + (size_t)b * L1c * INNERc, INNERc, acc);
}
__global__ __launch_bounds__(256) void k_projS(const float* __restrict__ X,
                                               const float* __restrict__ W) {
    int b = blockIdx.z;
    float acc[8][8];
    sgemm_block<false, false>(X + (size_t)b * L2c * Dc, W, Dc, Dc, INNERc, acc);
    store_tile(g_PS + (size_t)b * L2c * INNERc, INNERc, acc);
}

// 4a) wp[b,h] = relu(aff[b,h]^T @ pp[b,h])   (TN: M=j=512, N=d=128, K=i=512)  grid(1,4,128)
__global__ __launch_bounds__(256) void k_wp() {
    int bh = blockIdx.z, b = bh >> 3, h = bh & 7;
    float acc[8][8];
    sgemm_block<true, false>(g_aff + (size_t)bh * L1c * L2c,
                             g_PP + (size_t)b * L1c * INNERc + h * HDc,
                             L1c, L2c, INNERc, acc);
    store_tile_relu(g_wp + (size_t)bh * L2c * HDc, HDc, acc);
}
// 4b) ws[b,h] = relu(aff[b,h] @ ps[b,h])     (NN: M=i=512, N=d=128, K=j=512)  grid(1,4,128)
__global__ __launch_bounds__(256) void k_ws() {
    int bh = blockIdx.z, b = bh >> 3, h = bh & 7;
    float acc[8][8];
    sgemm_block<false, false>(g_aff + (size_t)bh * L1c * L2c,
                              g_PS + (size_t)b * L2c * INNERc + h * HDc,
                              L2c, L2c, INNERc, acc);
    store_tile_relu(g_ws + (size_t)bh * L1c * HDc, HDc, acc);
}

// 5) head max-pools
__global__ void k_poolp() {
    int idx = blockIdx.x * blockDim.x + threadIdx.x;
    const int tot = Bc * L2c * HDc;
    if (idx >= tot) return;
    int b = idx / (L2c * HDc);
    int r = idx - b * (L2c * HDc);
    float m = g_wp[((size_t)b * Hc) * L2c * HDc + r];
    #pragma unroll
    for (int h = 1; h < Hc; h++)
        m = fmaxf(m, g_wp[((size_t)(b * Hc + h)) * L2c * HDc + r]);
    g_poolp[idx] = m;
}
__global__ void k_pools() {
    int idx = blockIdx.x * blockDim.x + threadIdx.x;
    const int tot = Bc * L1c * HDc;
    if (idx >= tot) return;
    int b = idx / (L1c * HDc);
    int r = idx - b * (L1c * HDc);
    float m = g_ws[((size_t)b * Hc) * L1c * HDc + r];
    #pragma unroll
    for (int h = 1; h < Hc; h++)
        m = fmaxf(m, g_ws[((size_t)(b * Hc + h)) * L1c * HDc + r]);
    g_pools[idx] = m;
}

// 6) concats
__global__ void k_catp(const float* __restrict__ P) {
    int idx = blockIdx.x * blockDim.x + threadIdx.x;
    const int tot = Bc * L1c * DCc;
    if (idx >= tot) return;
    int bi = idx / DCc;        // b*512 + i
    int c  = idx - bi * DCc;
    g_catp[idx] = (c < Dc) ? P[(size_t)bi * Dc + c]
                           : g_pools[(size_t)bi * HDc + (c - Dc)];
}
__global__ void k_cats(const float* __restrict__ S) {
    int idx = blockIdx.x * blockDim.x + threadIdx.x;
    const int tot = Bc * L2c * DCc;
    if (idx >= tot) return;
    int bi = idx / DCc;
    int c  = idx - bi * DCc;
    g_cats[idx] = (c < Dc) ? S[(size_t)bi * Dc + c]
                           : g_poolp[(size_t)bi * HDc + (c - Dc)];
}

// 7) FFNs: out = relu(cat @ W + bias)    grid(4,4,16)
__global__ __launch_bounds__(256) void k_ffnp(const float* __restrict__ W,
                                              const float* __restrict__ bias,
                                              float* __restrict__ O) {
    int b = blockIdx.z;
    float acc[8][8];
    sgemm_block<false, false>(g_catp + (size_t)b * L1c * DCc, W, DCc, DCc, Dc, acc);
    int row0 = blockIdx.y * BM + ((threadIdx.x >> 4) << 3);
    int col0 = blockIdx.x * BN + ((threadIdx.x & 15) << 3);
    float bv[8];
    #pragma unroll
    for (int j = 0; j < 8; j++) bv[j] = bias[col0 + j];
    float* C = O + (size_t)b * L1c * Dc;
    #pragma unroll
    for (int i = 0; i < 8; i++) {
        float v[8];
        #pragma unroll
        for (int j = 0; j < 8; j++) v[j] = fmaxf(acc[i][j] + bv[j], 0.f);
        *(float4*)(C + (size_t)(row0 + i) * Dc + col0)     = make_float4(v[0], v[1], v[2], v[3]);
        *(float4*)(C + (size_t)(row0 + i) * Dc + col0 + 4) = make_float4(v[4], v[5], v[6], v[7]);
    }
}
__global__ __launch_bounds__(256) void k_ffns(const float* __restrict__ W,
                                              const float* __restrict__ bias,
                                              float* __restrict__ O) {
    int b = blockIdx.z;
    float acc[8][8];
    sgemm_block<false, false>(g_cats + (size_t)b * L2c * DCc, W, DCc, DCc, Dc, acc);
    int row0 = blockIdx.y * BM + ((threadIdx.x >> 4) << 3);
    int col0 = blockIdx.x * BN + ((threadIdx.x & 15) << 3);
    float bv[8];
    #pragma unroll
    for (int j = 0; j < 8; j++) bv[j] = bias[col0 + j];
    float* C = O + (size_t)b * L2c * Dc;
    #pragma unroll
    for (int i = 0; i < 8; i++) {
        float v[8];
        #pragma unroll
        for (int j = 0; j < 8; j++) v[j] = fmaxf(acc[i][j] + bv[j], 0.f);
        *(float4*)(C + (size_t)(row0 + i) * Dc + col0)     = make_float4(v[0], v[1], v[2], v[3]);
        *(float4*)(C + (size_t)(row0 + i) * Dc + col0 + 4) = make_float4(v[4], v[5], v[6], v[7]);
    }
}

// ---------------- launcher ----------------------------------------------------
extern "C" void kernel_launch(void* const* d_in, const int* in_sizes, int n_in,
                              void* d_out, int out_size) {
    const float* P    = (const float*)d_in[0];
    const float* S    = (const float*)d_in[1];
    const float* pm   = (const float*)d_in[2];
    const float* sm   = (const float*)d_in[3];
    const float* Waff = (const float*)d_in[4];
    const float* Wp   = (const float*)d_in[5];
    const float* Ws   = (const float*)d_in[6];
    const float* Wfp  = (const float*)d_in[7];
    const float* bfp  = (const float*)d_in[8];
    const float* Wfs  = (const float*)d_in[9];
    const float* bfs  = (const float*)d_in[10];

    float* outp = (float*)d_out;
    float* outs = outp + (size_t)Bc * L1c * Dc;

    dim3 blk(256);

    k_pw  <<<dim3(4, 4, Bc * Hc), blk>>>(P, Waff);
    k_aff <<<dim3(4, 4, Bc * Hc), blk>>>(S, pm, sm);
    k_projP<<<dim3(8, 4, Bc), blk>>>(P, Wp);
    k_projS<<<dim3(8, 4, Bc), blk>>>(S, Ws);
    k_wp  <<<dim3(1, 4, Bc * Hc), blk>>>();
    k_ws  <<<dim3(1, 4, Bc * Hc), blk>>>();

    {
        int tot = Bc * L2c * HDc;
        k_poolp<<<(tot + 255) / 256, 256>>>();
    }
    {
        int tot = Bc * L1c * HDc;
        k_pools<<<(tot + 255) / 256, 256>>>();
    }
    {
        int tot = Bc * L1c * DCc;
        k_catp<<<(tot + 255) / 256, 256>>>(P);
    }
    {
        int tot = Bc * L2c * DCc;
        k_cats<<<(tot + 255) / 256, 256>>>(S);
    }

    k_ffnp<<<dim3(4, 4, Bc), blk>>>(Wfp, bfp, outp);
    k_ffns<<<dim3(4, 4, Bc), blk>>>(Wfs, bfs, outs);
}